// round 11
// baseline (speedup 1.0000x reference)
#include <cuda_runtime.h>

// Problem constants
#define NCTA   128
#define TPB    256
#define NB     512
#define BT     4       // batch elements per CTA
#define NC     184     // cities
#define HH     32      // hidden
#define IND    14      // in_dim
#define DD     15      // in_dim + 1
#define NPRED  24
#define NHIST  24
#define NFEAT  13      // in_dim - 1
#define FTOT   48      // hist + pred

// Global scratch (per-CTA private slices; same-CTA produce/consume only)
__device__ float g_y0[(size_t)NCTA * NC * BT * 64];

// Shared memory layout (float offsets, all 16B-aligned where vector-loaded)
#define OFF_X    0        // 184*15*4 = 11040   x tile [c][k][b]
#define OFF_XIN  11040    // 2*512    = 1024    layer1 staged input, double-buffered
#define OFF_G    12064    // 2*4*128  = 1024    gate buffer [dir][b][j]
#define OFF_H    13088    // 4*32*4   = 512     h state [ld][k][b]
#define OFF_C    13600    // 4*32*4   = 512     c state [ld][k][b]
#define OFF_XN   14112    // 184*4    = 736     xn [c][b]
#define OFF_GX   14848    // 4*96     = 384
#define OFF_GH   15232    // 16*96    = 1536
#define OFF_U    16768    // 4*16     = 64
#define OFF_Y1   16832    // 184*4*32 = 23552   y1 forward half [c][b][j]
#define SMEM_FLOATS 40384 // 161,536 bytes

typedef unsigned long long u64;

__device__ __forceinline__ u64 pk2(float w) {
    u64 r;
    asm("mov.b64 %0, {%1, %1};" : "=l"(r) : "f"(w));
    return r;
}
__device__ __forceinline__ void ffma2(u64& a, u64 x, u64 w) {
    asm("fma.rn.f32x2 %0, %1, %2, %0;" : "+l"(a) : "l"(x), "l"(w));
}
__device__ __forceinline__ u64 addx2(u64 a, u64 b) {
    u64 r;
    asm("add.rn.f32x2 %0, %1, %2;" : "=l"(r) : "l"(a), "l"(b));
    return r;
}
__device__ __forceinline__ float2 unpk(u64 a) {
    float2 f;
    asm("mov.b64 {%0, %1}, %2;" : "=f"(f.x), "=f"(f.y) : "l"(a));
    return f;
}

// hardware tanh (MUFU.TANH, sm_90+): single instruction
__device__ __forceinline__ float tanha(float x) {
    float r;
    asm("tanh.approx.f32 %0, %1;" : "=f"(r) : "f"(x));
    return r;
}
// sigmoid(x) = 0.5*tanh(0.5x) + 0.5 : 1 MUFU + 2 FMA
__device__ __forceinline__ float sigf(float x) {
    return fmaf(0.5f, tanha(0.5f * x), 0.5f);
}
__device__ __forceinline__ float tanhfast(float x) {
    return tanha(x);
}

__global__ void __launch_bounds__(TPB, 1)
bilstm_kernel(const float* __restrict__ rain_hist,
              const float* __restrict__ feature,
              const float* __restrict__ h0,
              const float* __restrict__ c0,
              const float* __restrict__ W_mlp,
              const float* __restrict__ b_mlp,
              const float* __restrict__ Wih_g,
              const float* __restrict__ Whh_g,
              const float* __restrict__ b_ih_g,
              const float* __restrict__ b_hh_g,
              const float* __restrict__ Wih0,
              const float* __restrict__ Whh0,
              const float* __restrict__ b0,
              const float* __restrict__ Wih1,
              const float* __restrict__ Whh1,
              const float* __restrict__ b1,
              const float* __restrict__ W_fc,
              const float* __restrict__ b_fc,
              float* __restrict__ out)
{
    extern __shared__ float sm[];
    float* sX   = sm + OFF_X;
    float* sXin = sm + OFF_XIN;
    float* sG   = sm + OFF_G;
    float* sH   = sm + OFF_H;
    float* sCst = sm + OFF_C;
    float* sXN  = sm + OFF_XN;
    float* sGX  = sm + OFF_GX;
    float* sGH  = sm + OFF_GH;
    float* sU   = sm + OFF_U;
    float* sY1  = sm + OFF_Y1;

    const int tid = threadIdx.x;
    const int cta = blockIdx.x;
    const int bg  = cta * BT;

    const int dirg = tid >> 7;   // gate-phase: direction
    const int jg   = tid & 127;  // gate-phase: gate row
    const int bu   = (tid >> 5) & 3;  // update-phase: batch
    const int ju   = tid & 31;        // update-phase: hidden index
    const int row  = dirg * 128 + jg; // gate row id (per dir)

    // ---- per-thread weight rows in REGISTERS ----
    float w0x[DD], w0h[HH], bias0;
    float w1x[64], w1h[HH], bias1;
#pragma unroll
    for (int k = 0; k < DD; ++k) w0x[k] = Wih0[row * DD + k];
#pragma unroll
    for (int k = 0; k < HH; ++k) w0h[k] = Whh0[row * HH + k];
    bias0 = b0[row];
#pragma unroll
    for (int k = 0; k < 64; ++k) w1x[k] = Wih1[row * 64 + k];
#pragma unroll
    for (int k = 0; k < HH; ++k) w1h[k] = Whh1[row * HH + k];
    bias1 = b1[row];

    // ---- initial states ----
    for (int e = tid; e < 4 * HH * BT; e += TPB) {
        int ld = e >> 7, k = (e >> 2) & 31, b = e & 3;
        sH[(ld * HH + k) * BT + b]   = h0[((size_t)ld * NB + bg + b) * HH + k];
        sCst[(ld * HH + k) * BT + b] = c0[((size_t)ld * NB + bg + b) * HH + k];
    }
    for (int e = tid; e < NC * BT; e += TPB) {
        int c = e >> 2, b = e & 3;
        sXN[c * BT + b] = rain_hist[((size_t)(bg + b) * NHIST + (NHIST - 1)) * NC + c];
    }
    __syncthreads();

    for (int t = 0; t < NPRED; ++t) {
        // ============ Phase 1: build x tile (slot0=g later, slot1=xn, 2..14=feat) ============
        for (int e = tid; e < NC * NFEAT * BT; e += TPB) {
            int b = e / (NC * NFEAT);
            int rem = e - b * (NC * NFEAT);
            int c = rem / NFEAT;
            int kk = rem - c * NFEAT;
            sX[(c * DD + 2 + kk) * BT + b] =
                feature[(((size_t)(bg + b) * FTOT + NHIST + t) * NC + c) * NFEAT + kk];
        }
        for (int e = tid; e < NC * BT; e += TPB) {
            int c = e >> 2, b = e & 3;
            sX[(c * DD + 1) * BT + b] = sXN[c * BT + b];
        }
        __syncthreads();

        // ============ Phase 2: gated graph MLP (4-way c-split chains) ============
        if (tid < NC) {
            const int j = tid;
            u64 A0 = pk2(b_mlp[j]), A1 = 0, A2 = 0, A3 = 0;
            u64 B0 = A0, B1 = 0, B2 = 0, B3 = 0;
            const float* wbase = W_mlp + j;
            for (int c = 0; c < NC; c += 4) {
#pragma unroll
                for (int p = 0; p < 4; ++p) {
                    const ulonglong2* xp = (const ulonglong2*)(sX + ((c + p) * DD + 1) * BT);
                    const float* wp = wbase + (size_t)(c + p) * IND * NC;
#pragma unroll
                    for (int kk = 0; kk < IND; ++kk) {
                        u64 w = pk2(wp[(size_t)kk * NC]);
                        ulonglong2 xv = xp[kk];
                        if (p == 0) { ffma2(A0, xv.x, w); ffma2(B0, xv.y, w); }
                        if (p == 1) { ffma2(A1, xv.x, w); ffma2(B1, xv.y, w); }
                        if (p == 2) { ffma2(A2, xv.x, w); ffma2(B2, xv.y, w); }
                        if (p == 3) { ffma2(A3, xv.x, w); ffma2(B3, xv.y, w); }
                    }
                }
            }
            float2 v01 = unpk(addx2(addx2(A0, A1), addx2(A2, A3)));
            float2 v23 = unpk(addx2(addx2(B0, B1), addx2(B2, B3)));
            sX[(j * DD) * BT + 0] = sigf(v01.x);
            sX[(j * DD) * BT + 1] = sigf(v01.y);
            sX[(j * DD) * BT + 2] = sigf(v23.x);
            sX[(j * DD) * BT + 3] = sigf(v23.y);
        }
        __syncthreads();

        // ============ Phase 3: GRU cell ============
        for (int e = tid; e < BT * DD; e += TPB) {
            int b = e / DD, k = e - b * DD;
            float s = 0.0f;
            for (int c = 0; c < NC; ++c) s += sX[(c * DD + k) * BT + b];
            sU[b * 16 + k] = s * (1.0f / NC);
        }
        __syncthreads();
        for (int e = tid; e < BT * 96; e += TPB) {
            int b = e / 96, j = e - b * 96;
            float a = b_ih_g[j];
#pragma unroll
            for (int k = 0; k < DD; ++k)
                a = fmaf(sU[b * 16 + k], Wih_g[k * 96 + j], a);
            sGX[e] = a;
        }
        for (int e = tid; e < 16 * 96; e += TPB) {
            int lb = e / 96, j = e - lb * 96;
            int l = lb >> 2, b = lb & 3;
            float a = b_hh_g[j];
#pragma unroll
            for (int k = 0; k < HH; ++k)
                a = fmaf(sH[(l * HH + k) * BT + b], Whh_g[k * 96 + j], a);
            sGH[e] = a;
        }
        __syncthreads();
        for (int e = tid; e < 4 * BT * HH; e += TPB) {
            int l = e >> 7, b = (e >> 5) & 3, j = e & 31;
            int gb = b * 96, ghb = (l * BT + b) * 96;
            float r = sigf(sGX[gb + j]      + sGH[ghb + j]);
            float z = sigf(sGX[gb + 32 + j] + sGH[ghb + 32 + j]);
            float n = tanhfast(sGX[gb + 64 + j] + r * sGH[ghb + 64 + j]);
            int hi = (l * HH + j) * BT + b;
            sH[hi] = (1.0f - z) * n + z * sH[hi];
        }
        __syncthreads();

        // ============ Phase 4: BiLSTM layer 0 — x-part hoisted into window ============
        {
            const ulonglong2* hp = (const ulonglong2*)(sH + dirg * HH * BT);
            u64 x01, x23;
            {   // x-part prologue for s = 0
                int city = dirg ? (NC - 1) : 0;
                const ulonglong2* xp = (const ulonglong2*)(sX + city * DD * BT);
                x01 = pk2(bias0); x23 = x01;
#pragma unroll
                for (int k = 0; k < DD; ++k) {
                    u64 w = pk2(w0x[k]);
                    ulonglong2 xv = xp[k];
                    ffma2(x01, xv.x, w); ffma2(x23, xv.y, w);
                }
            }
            for (int s = 0; s < NC; ++s) {
                // critical segment: h-part only (32 deep)
                u64 a01 = x01, a23 = x23;
#pragma unroll
                for (int k = 0; k < HH; ++k) {
                    u64 w = pk2(w0h[k]);
                    ulonglong2 hv = hp[k];
                    ffma2(a01, hv.x, w); ffma2(a23, hv.y, w);
                }
                float2 v01 = unpk(a01), v23 = unpk(a23);
                float* gp = sG + dirg * 512 + jg;
                gp[0] = v01.x; gp[128] = v01.y; gp[256] = v23.x; gp[384] = v23.y;
                __syncthreads();
                // window: update(s) + x-part(s+1)
                {
                    const int du = tid >> 7;
                    const int cityu = du ? (NC - 1 - s) : s;
                    const float* g = sG + du * 512 + bu * 128;
                    float iv = sigf(g[ju]);
                    float fv = sigf(g[32 + ju]);
                    float gv = tanhfast(g[64 + ju]);
                    float ov = sigf(g[96 + ju]);
                    int ci = (du * HH + ju) * BT + bu;
                    float cc = fmaf(fv, sCst[ci], iv * gv);
                    sCst[ci] = cc;
                    float hh2 = ov * tanhfast(cc);
                    sH[ci] = hh2;
                    g_y0[((size_t)(cta * NC + cityu) * BT + bu) * 64 + du * 32 + ju] = hh2;
                }
                if (s + 1 < NC) {
                    int cityn = dirg ? (NC - 2 - s) : (s + 1);
                    const ulonglong2* xp = (const ulonglong2*)(sX + cityn * DD * BT);
                    x01 = pk2(bias0); x23 = x01;
#pragma unroll
                    for (int k = 0; k < DD; ++k) {
                        u64 w = pk2(w0x[k]);
                        ulonglong2 xv = xp[k];
                        ffma2(x01, xv.x, w); ffma2(x23, xv.y, w);
                    }
                }
                __syncthreads();
            }
        }

        // ============ Phase 5: BiLSTM layer 1 — input-part hoisted, 2-deep staging ====
        {
            // stage step 0 into buf0, step 1 into buf1
            for (int q = 0; q < 2; ++q) {
                int e = tid * 2 + q;
                int ci = e >> 8, r = e & 255, k = r >> 2, b = r & 3;
                int city0 = ci ? (NC - 1) : 0;
                int city1 = ci ? (NC - 2) : 1;
                sXin[e]       = g_y0[((size_t)(cta * NC + city0) * BT + b) * 64 + k];
                sXin[512 + e] = g_y0[((size_t)(cta * NC + city1) * BT + b) * 64 + k];
            }
            __syncthreads();
            const ulonglong2* hp = (const ulonglong2*)(sH + (2 + dirg) * HH * BT);
            u64 xp01, xp23;
            {   // input-part for s = 0 from buf0
                const ulonglong2* xp = (const ulonglong2*)(sXin + dirg * 256);
                xp01 = pk2(bias1); xp23 = xp01;
#pragma unroll
                for (int k = 0; k < 64; ++k) {
                    u64 w = pk2(w1x[k]);
                    ulonglong2 xv = xp[k];
                    ffma2(xp01, xv.x, w); ffma2(xp23, xv.y, w);
                }
            }
            // prefetch step 2
            float pf0, pf1;
            {
                int e = tid * 2;
                int ci = e >> 8, r = e & 255, k = r >> 2, b = r & 3;
                int city = ci ? (NC - 3) : 2;
                pf0 = g_y0[((size_t)(cta * NC + city) * BT + b) * 64 + k];
                e = tid * 2 + 1;
                ci = e >> 8; r = e & 255; k = r >> 2; b = r & 3;
                city = ci ? (NC - 3) : 2;
                pf1 = g_y0[((size_t)(cta * NC + city) * BT + b) * 64 + k];
            }
            for (int s = 0; s < NC; ++s) {
                // critical segment: h-part only (32 deep)
                u64 a01 = xp01, a23 = xp23;
#pragma unroll
                for (int k = 0; k < HH; ++k) {
                    u64 w = pk2(w1h[k]);
                    ulonglong2 hv = hp[k];
                    ffma2(a01, hv.x, w); ffma2(a23, hv.y, w);
                }
                float2 v01 = unpk(a01), v23 = unpk(a23);
                float* gp = sG + dirg * 512 + jg;
                gp[0] = v01.x; gp[128] = v01.y; gp[256] = v23.x; gp[384] = v23.y;
                __syncthreads();
                // window: stash step s+2, update(s), prefetch step s+3, input-part(s+1)
                if (s + 2 < NC)
                    *(float2*)(sXin + (s & 1) * 512 + tid * 2) = make_float2(pf0, pf1);
                {
                    const int du = tid >> 7;
                    const float* g = sG + du * 512 + bu * 128;
                    float iv = sigf(g[ju]);
                    float fv = sigf(g[32 + ju]);
                    float gv = tanhfast(g[64 + ju]);
                    float ov = sigf(g[96 + ju]);
                    int ci = ((2 + du) * HH + ju) * BT + bu;
                    float cc = fmaf(fv, sCst[ci], iv * gv);
                    sCst[ci] = cc;
                    float hh2 = ov * tanhfast(cc);
                    sH[ci] = hh2;
                    if (du == 0)  // only forward half of y1 is consumed
                        sY1[(s * BT + bu) * 32 + ju] = hh2;
                }
                {
                    const int sp = (s + 3 < NC) ? (s + 3) : (NC - 1);
                    int e = tid * 2;
                    int ci = e >> 8, r = e & 255, k = r >> 2, b = r & 3;
                    int city = ci ? (NC - 1 - sp) : sp;
                    pf0 = g_y0[((size_t)(cta * NC + city) * BT + b) * 64 + k];
                    e = tid * 2 + 1;
                    ci = e >> 8; r = e & 255; k = r >> 2; b = r & 3;
                    city = ci ? (NC - 1 - sp) : sp;
                    pf1 = g_y0[((size_t)(cta * NC + city) * BT + b) * 64 + k];
                }
                if (s + 1 < NC) {
                    const ulonglong2* xp =
                        (const ulonglong2*)(sXin + ((s + 1) & 1) * 512 + dirg * 256);
                    xp01 = pk2(bias1); xp23 = xp01;
#pragma unroll
                    for (int k = 0; k < 64; ++k) {
                        u64 w = pk2(w1x[k]);
                        ulonglong2 xv = xp[k];
                        ffma2(xp01, xv.x, w); ffma2(xp23, xv.y, w);
                    }
                }
                __syncthreads();
            }
        }

        // ============ Phase 6: FC head -> xn, write output ============
        {
            const float bfc = b_fc[0];
            for (int e = tid; e < NC * BT; e += TPB) {
                int c = e >> 2, b = e & 3;
                float a = bfc;
                const float* yp = sY1 + (c * BT + b) * 32;
#pragma unroll
                for (int j = 0; j < HH; ++j)
                    a = fmaf(yp[j], W_fc[j], a);
                sXN[c * BT + b] = a;
                out[((size_t)(bg + b) * NPRED + t) * NC + c] = a;
            }
        }
        __syncthreads();
    }
}

extern "C" void kernel_launch(void* const* d_in, const int* in_sizes, int n_in,
                              void* d_out, int out_size) {
    (void)in_sizes; (void)n_in; (void)out_size;
    const float* rain_hist = (const float*)d_in[0];
    const float* feature   = (const float*)d_in[1];
    const float* h0        = (const float*)d_in[2];
    const float* c0        = (const float*)d_in[3];
    const float* W_mlp     = (const float*)d_in[4];
    const float* b_mlp     = (const float*)d_in[5];
    const float* Wih_g     = (const float*)d_in[6];
    const float* Whh_g     = (const float*)d_in[7];
    const float* b_ih_g    = (const float*)d_in[8];
    const float* b_hh_g    = (const float*)d_in[9];
    const float* Wih0      = (const float*)d_in[10];
    const float* Whh0      = (const float*)d_in[11];
    const float* b0        = (const float*)d_in[12];
    const float* Wih1      = (const float*)d_in[13];
    const float* Whh1      = (const float*)d_in[14];
    const float* b1        = (const float*)d_in[15];
    const float* W_fc      = (const float*)d_in[16];
    const float* b_fc      = (const float*)d_in[17];

    size_t smem = (size_t)SMEM_FLOATS * sizeof(float);
    cudaFuncSetAttribute(bilstm_kernel,
                         cudaFuncAttributeMaxDynamicSharedMemorySize, (int)smem);

    bilstm_kernel<<<NCTA, TPB, smem>>>(
        rain_hist, feature, h0, c0, W_mlp, b_mlp,
        Wih_g, Whh_g, b_ih_g, b_hh_g,
        Wih0, Whh0, b0, Wih1, Whh1, b1,
        W_fc, b_fc, (float*)d_out);
}